// round 12
// baseline (speedup 1.0000x reference)
#include <cuda_runtime.h>

namespace {

constexpr int BATCH = 16;
constexpr int DIM   = 48;
constexpr int HID   = 16;
constexpr int CC    = 8;
constexpr int Hh    = 256;
constexpr int Ww    = 256;
constexpr int HW    = Hh * Ww;
constexpr float LN_EPS = 1e-5f;
constexpr int THREADS = 256;
constexpr int TPB1   = 128;   // tokens per block in k_front (2 threads/token)
constexpr int XSTRIDE = 52;   // padded token stride in smem floats

// intermediate, token-interleaved: g_mid[token][16]; ch 0..7 = x1, 8..15 = LN(x2)
__device__ float g_mid[(size_t)BATCH * HW * HID];

__device__ __forceinline__ float gelu_f(float v) {
    return 0.5f * v * (1.0f + erff(v * 0.70710678118654752440f));
}

// ---- packed f32x2 helpers ----
__device__ __forceinline__ unsigned long long pk2(float lo, float hi) {
    unsigned long long r;
    asm("mov.b64 %0, {%1, %2};" : "=l"(r) : "f"(lo), "f"(hi));
    return r;
}
__device__ __forceinline__ void upk2(unsigned long long v, float& lo, float& hi) {
    asm("mov.b64 {%0, %1}, %2;" : "=f"(lo), "=f"(hi) : "l"(v));
}
__device__ __forceinline__ void ffma2(unsigned long long& d,
                                      unsigned long long a, unsigned long long b) {
    asm("fma.rn.f32x2 %0, %1, %2, %3;" : "=l"(d) : "l"(a), "l"(b), "l"(d));
}

// ---------------- Kernel 1: token GEMM 48->16 (2 threads/token), GELUx2, LN ----------------
__global__ __launch_bounds__(THREADS, 5)
void k_front(const float* __restrict__ x,
             const float* __restrict__ gW1, const float* __restrict__ gb1,
             const float* __restrict__ ggamma, const float* __restrict__ gbeta)
{
    __shared__ __align__(16) float sW1[DIM * HID];
    __shared__ float sb1[HID];
    __shared__ float sG[CC], sBt[CC];
    extern __shared__ __align__(16) float sX[];      // 128 tokens * 52 floats

    const int tid = threadIdx.x;
    for (int i = tid; i < DIM * HID; i += THREADS) sW1[i] = gW1[i];
    if (tid < HID) sb1[tid] = gb1[tid];
    if (tid < CC)  { sG[tid] = ggamma[tid]; sBt[tid] = gbeta[tid]; }

    // coalesced stage: this block's 128 tokens (128*12 float4)
    const float4* xg4 = (const float4*)x;
    const size_t base4 = (size_t)blockIdx.x * TPB1 * (DIM / 4);
    #pragma unroll
    for (int i = tid; i < TPB1 * (DIM / 4); i += THREADS) {
        const int tok = i / (DIM / 4);
        const int e4  = i - tok * (DIM / 4);
        *(float4*)(sX + tok * XSTRIDE + e4 * 4) = xg4[base4 + i];
    }
    __syncthreads();

    const int role = tid >> 7;            // 0: x1 half (cols 0-7), 1: x2 half (cols 8-15) + LN
    const int lt   = tid & (TPB1 - 1);
    const int jbase = role * CC;
    const float4* xp = (const float4*)(sX + lt * XSTRIDE);

    unsigned long long yp[4];
    yp[0] = pk2(sb1[jbase + 0], sb1[jbase + 1]);
    yp[1] = pk2(sb1[jbase + 2], sb1[jbase + 3]);
    yp[2] = pk2(sb1[jbase + 4], sb1[jbase + 5]);
    yp[3] = pk2(sb1[jbase + 6], sb1[jbase + 7]);

    #pragma unroll 1
    for (int ch = 0; ch < 3; ++ch) {
        const float4 v0 = xp[ch * 4 + 0], v1 = xp[ch * 4 + 1],
                     v2 = xp[ch * 4 + 2], v3 = xp[ch * 4 + 3];
        const float xs[16] = {v0.x, v0.y, v0.z, v0.w, v1.x, v1.y, v1.z, v1.w,
                              v2.x, v2.y, v2.z, v2.w, v3.x, v3.y, v3.z, v3.w};
        #pragma unroll
        for (int k = 0; k < 16; ++k) {
            const int d = ch * 16 + k;
            const ulonglong2* wp = (const ulonglong2*)(sW1 + d * HID + jbase);
            const ulonglong2 wA = wp[0], wB = wp[1];
            const unsigned long long xv2 = pk2(xs[k], xs[k]);
            ffma2(yp[0], xv2, wA.x);
            ffma2(yp[1], xv2, wA.y);
            ffma2(yp[2], xv2, wB.x);
            ffma2(yp[3], xv2, wB.y);
        }
    }

    float y[CC];
    upk2(yp[0], y[0], y[1]);
    upk2(yp[1], y[2], y[3]);
    upk2(yp[2], y[4], y[5]);
    upk2(yp[3], y[6], y[7]);

    #pragma unroll
    for (int j = 0; j < CC; ++j) y[j] = gelu_f(gelu_f(y[j]));

    const int t = blockIdx.x * TPB1 + lt;              // token id
    float* mb = g_mid + (size_t)t * HID + role * CC;   // contiguous 8 floats

    if (role == 0) {
        *(float4*)(mb + 0) = make_float4(y[0], y[1], y[2], y[3]);
        *(float4*)(mb + 4) = make_float4(y[4], y[5], y[6], y[7]);
    } else {
        float m = 0.0f;
        #pragma unroll
        for (int c = 0; c < CC; ++c) m += y[c];
        m *= 0.125f;
        float var = 0.0f;
        #pragma unroll
        for (int c = 0; c < CC; ++c) { const float dd = y[c] - m; var = fmaf(dd, dd, var); }
        const float inv = rsqrtf(var * 0.125f + LN_EPS);
        float n[CC];
        #pragma unroll
        for (int c = 0; c < CC; ++c) n[c] = (y[c] - m) * inv * sG[c] + sBt[c];
        *(float4*)(mb + 0) = make_float4(n[0], n[1], n[2], n[3]);
        *(float4*)(mb + 4) = make_float4(n[4], n[5], n[6], n[7]);
    }
}

// ---------------- Kernel 2: dw3x3 + pw1x1 + gate + GEMM 8->48 ----------------
constexpr int TH2 = 8;
constexpr int TW2 = 32;
constexpr int PH2 = TH2 + 2;   // 10
constexpr int PW2 = TW2 + 2;   // 34
constexpr int NT2 = PH2 * PW2; // 340

__global__ __launch_bounds__(THREADS, 4)
void k_back(const float* __restrict__ gdww, const float* __restrict__ gdwb,
            const float* __restrict__ gpww, const float* __restrict__ gpwb,
            const float* __restrict__ gW2, const float* __restrict__ gb2,
            float* __restrict__ out)
{
    __shared__ __align__(16) float sTile[NT2 * CC];    // pixel-major [p][8ch] (10880 B)
    __shared__ __align__(16) float sW2[CC * DIM];
    __shared__ __align__(16) float sb2[DIM];
    __shared__ __align__(16) float sDwT[9 * CC];       // dw weights transposed [tap][c]
    __shared__ float sPw[CC * CC], sPwb[CC];
    __shared__ float sDwb[CC];

    const int tid = threadIdx.x;
    for (int i = tid; i < CC * DIM; i += THREADS) sW2[i] = gW2[i];
    if (tid < DIM)     sb2[tid] = gb2[tid];
    if (tid < CC * CC) sPw[tid] = gpww[tid];
    if (tid < CC * 9) {                                 // gdww[c][tap] -> sDwT[tap][c]
        const int c = tid / 9, tap = tid - c * 9;
        sDwT[tap * CC + c] = gdww[tid];
    }
    if (tid < CC)      { sPwb[tid] = gpwb[tid]; sDwb[tid] = gdwb[tid]; }

    const int b  = blockIdx.z;
    const int h0 = blockIdx.y * TH2;
    const int w0 = blockIdx.x * TW2;

    // halo'd tile fill: 2 LDG.128 -> 2 STS.128 per pixel
    #pragma unroll 1
    for (int p = tid; p < NT2; p += THREADS) {
        const int py = p / PW2;
        const int px = p - py * PW2;
        const int gh = h0 + py - 1;
        const int gw = w0 + px - 1;
        float4 a = make_float4(0.f, 0.f, 0.f, 0.f);
        float4 bq = a;
        if ((unsigned)gh < (unsigned)Hh && (unsigned)gw < (unsigned)Ww) {
            const float* mp = g_mid + (size_t)(b * HW + gh * Ww + gw) * HID + CC;
            a  = *(const float4*)(mp + 0);
            bq = *(const float4*)(mp + 4);
        }
        *(float4*)(sTile + p * CC + 0) = a;
        *(float4*)(sTile + p * CC + 4) = bq;
    }
    __syncthreads();

    const int ty = tid >> 5;
    const int tx = tid & 31;
    const int pix = (h0 + ty) * Ww + (w0 + tx);

    // ---- dw 3x3 over taps: per tap 2 LDS.128 (tile) + 2 broadcast LDS.128 (wts) + 8 FMA ----
    float acc[CC], ncen[CC];
    #pragma unroll
    for (int c = 0; c < CC; ++c) acc[c] = sDwb[c];

    #pragma unroll
    for (int dy = 0; dy < 3; ++dy) {
        #pragma unroll
        for (int dx = 0; dx < 3; ++dx) {
            const float* tp = sTile + ((ty + dy) * PW2 + (tx + dx)) * CC;
            const float4 ta = *(const float4*)(tp + 0);
            const float4 tb = *(const float4*)(tp + 4);
            const float* wt = sDwT + (dy * 3 + dx) * CC;
            const float4 wa = *(const float4*)(wt + 0);
            const float4 wb = *(const float4*)(wt + 4);
            acc[0] = fmaf(ta.x, wa.x, acc[0]);
            acc[1] = fmaf(ta.y, wa.y, acc[1]);
            acc[2] = fmaf(ta.z, wa.z, acc[2]);
            acc[3] = fmaf(ta.w, wa.w, acc[3]);
            acc[4] = fmaf(tb.x, wb.x, acc[4]);
            acc[5] = fmaf(tb.y, wb.y, acc[5]);
            acc[6] = fmaf(tb.z, wb.z, acc[6]);
            acc[7] = fmaf(tb.w, wb.w, acc[7]);
            if (dy == 1 && dx == 1) {
                ncen[0] = ta.x; ncen[1] = ta.y; ncen[2] = ta.z; ncen[3] = ta.w;
                ncen[4] = tb.x; ncen[5] = tb.y; ncen[6] = tb.z; ncen[7] = tb.w;
            }
        }
    }

    // ---- pw 1x1 (scalar, proven) ----
    float chv[CC];
    #pragma unroll
    for (int c = 0; c < CC; ++c) {
        float v = sPwb[c];
        #pragma unroll
        for (int cin = 0; cin < CC; ++cin)
            v = fmaf(ncen[cin], sPw[c * CC + cin], v);
        chv[c] = v;
    }

    // own token's x1 half: 32 contiguous bytes
    const float4* xq = (const float4*)(g_mid + (size_t)(b * HW + pix) * HID);
    const float4 x1a = __ldg(xq + 0);
    const float4 x1b = __ldg(xq + 1);
    const float x1[CC] = {x1a.x, x1a.y, x1a.z, x1a.w, x1b.x, x1b.y, x1b.z, x1b.w};

    float g[CC];
    #pragma unroll
    for (int c = 0; c < CC; ++c) g[c] = x1[c] * acc[c] * chv[c];

    // ---- GEMM 8->48 + planar NCHW stores ----
    float* op = out + (size_t)b * DIM * HW + pix;
    #pragma unroll
    for (int d4 = 0; d4 < DIM / 4; ++d4) {
        float4 a4 = *(const float4*)(sb2 + d4 * 4);
        #pragma unroll
        for (int c = 0; c < CC; ++c) {
            const float4 wv = *(const float4*)(sW2 + c * DIM + d4 * 4);
            const float gc = g[c];
            a4.x = fmaf(gc, wv.x, a4.x);
            a4.y = fmaf(gc, wv.y, a4.y);
            a4.z = fmaf(gc, wv.z, a4.z);
            a4.w = fmaf(gc, wv.w, a4.w);
        }
        op[(size_t)(d4 * 4 + 0) * HW] = a4.x;
        op[(size_t)(d4 * 4 + 1) * HW] = a4.y;
        op[(size_t)(d4 * 4 + 2) * HW] = a4.z;
        op[(size_t)(d4 * 4 + 3) * HW] = a4.w;
    }
}

} // namespace

extern "C" void kernel_launch(void* const* d_in, const int* in_sizes, int n_in,
                              void* d_out, int out_size) {
    const float* x     = (const float*)d_in[0];
    const float* W1    = (const float*)d_in[1];
    const float* b1    = (const float*)d_in[2];
    const float* gamma = (const float*)d_in[3];
    const float* beta  = (const float*)d_in[4];
    const float* dw_w  = (const float*)d_in[5];
    const float* dw_b  = (const float*)d_in[6];
    const float* pw_w  = (const float*)d_in[7];
    const float* pw_b  = (const float*)d_in[8];
    const float* W2    = (const float*)d_in[9];
    const float* b2    = (const float*)d_in[10];
    float* out = (float*)d_out;

    const int dyn1 = TPB1 * XSTRIDE * (int)sizeof(float);   // 26624 B
    cudaFuncSetAttribute(k_front, cudaFuncAttributeMaxDynamicSharedMemorySize, dyn1);

    k_front<<<BATCH * HW / TPB1, THREADS, dyn1>>>(x, W1, b1, gamma, beta);

    dim3 grid2(Ww / TW2, Hh / TH2, BATCH);
    k_back<<<grid2, THREADS>>>(dw_w, dw_b, pw_w, pw_b, W2, b2, out);
}

// round 14
// speedup vs baseline: 1.0614x; 1.0614x over previous
#include <cuda_runtime.h>

namespace {

constexpr int BATCH = 16;
constexpr int DIM   = 48;
constexpr int HID   = 16;
constexpr int CC    = 8;
constexpr int Hh    = 256;
constexpr int Ww    = 256;
constexpr int HW    = Hh * Ww;
constexpr float LN_EPS = 1e-5f;
constexpr int THREADS = 256;
constexpr int TPB1   = 128;   // tokens per block in k_front (2 threads/token)
constexpr int XSTRIDE = 52;   // padded token stride in smem floats

// intermediate, token-interleaved: g_mid[token][16]; ch 0..7 = x1, 8..15 = LN(x2)
__device__ float g_mid[(size_t)BATCH * HW * HID];

__device__ __forceinline__ float gelu_f(float v) {
    return 0.5f * v * (1.0f + erff(v * 0.70710678118654752440f));
}

// ---- packed f32x2 helpers ----
__device__ __forceinline__ unsigned long long pk2(float lo, float hi) {
    unsigned long long r;
    asm("mov.b64 %0, {%1, %2};" : "=l"(r) : "f"(lo), "f"(hi));
    return r;
}
__device__ __forceinline__ void upk2(unsigned long long v, float& lo, float& hi) {
    asm("mov.b64 {%0, %1}, %2;" : "=f"(lo), "=f"(hi) : "l"(v));
}
__device__ __forceinline__ void ffma2(unsigned long long& d,
                                      unsigned long long a, unsigned long long b) {
    asm("fma.rn.f32x2 %0, %1, %2, %3;" : "=l"(d) : "l"(a), "l"(b), "l"(d));
}

// ---------------- Kernel 1: token GEMM 48->16 (2 threads/token), GELUx2, LN ----------------
__global__ __launch_bounds__(THREADS, 4)
void k_front(const float* __restrict__ x,
             const float* __restrict__ gW1, const float* __restrict__ gb1,
             const float* __restrict__ ggamma, const float* __restrict__ gbeta)
{
    __shared__ __align__(16) float sW1[DIM * HID];
    __shared__ float sb1[HID];
    __shared__ float sG[CC], sBt[CC];
    extern __shared__ __align__(16) float sX[];      // 128 tokens * 52 floats

    const int tid = threadIdx.x;
    for (int i = tid; i < DIM * HID; i += THREADS) sW1[i] = gW1[i];
    if (tid < HID) sb1[tid] = gb1[tid];
    if (tid < CC)  { sG[tid] = ggamma[tid]; sBt[tid] = gbeta[tid]; }

    // coalesced stage: this block's 128 tokens (128*12 float4)
    const float4* xg4 = (const float4*)x;
    const size_t base4 = (size_t)blockIdx.x * TPB1 * (DIM / 4);
    #pragma unroll
    for (int i = tid; i < TPB1 * (DIM / 4); i += THREADS) {
        const int tok = i / (DIM / 4);
        const int e4  = i - tok * (DIM / 4);
        *(float4*)(sX + tok * XSTRIDE + e4 * 4) = xg4[base4 + i];
    }
    __syncthreads();

    const int role = tid >> 7;            // 0: x1 half (cols 0-7), 1: x2 half (cols 8-15) + LN
    const int lt   = tid & (TPB1 - 1);
    const int jbase = role * CC;
    const float4* xp = (const float4*)(sX + lt * XSTRIDE);

    unsigned long long yp[4];
    yp[0] = pk2(sb1[jbase + 0], sb1[jbase + 1]);
    yp[1] = pk2(sb1[jbase + 2], sb1[jbase + 3]);
    yp[2] = pk2(sb1[jbase + 4], sb1[jbase + 5]);
    yp[3] = pk2(sb1[jbase + 6], sb1[jbase + 7]);

    #pragma unroll 1
    for (int ch = 0; ch < 3; ++ch) {
        const float4 v0 = xp[ch * 4 + 0], v1 = xp[ch * 4 + 1],
                     v2 = xp[ch * 4 + 2], v3 = xp[ch * 4 + 3];
        const float xs[16] = {v0.x, v0.y, v0.z, v0.w, v1.x, v1.y, v1.z, v1.w,
                              v2.x, v2.y, v2.z, v2.w, v3.x, v3.y, v3.z, v3.w};
        #pragma unroll
        for (int k = 0; k < 16; ++k) {
            const int d = ch * 16 + k;
            const ulonglong2* wp = (const ulonglong2*)(sW1 + d * HID + jbase);
            const ulonglong2 wA = wp[0], wB = wp[1];
            const unsigned long long xv2 = pk2(xs[k], xs[k]);
            ffma2(yp[0], xv2, wA.x);
            ffma2(yp[1], xv2, wA.y);
            ffma2(yp[2], xv2, wB.x);
            ffma2(yp[3], xv2, wB.y);
        }
    }

    float y[CC];
    upk2(yp[0], y[0], y[1]);
    upk2(yp[1], y[2], y[3]);
    upk2(yp[2], y[4], y[5]);
    upk2(yp[3], y[6], y[7]);

    #pragma unroll
    for (int j = 0; j < CC; ++j) y[j] = gelu_f(gelu_f(y[j]));

    const int t = blockIdx.x * TPB1 + lt;              // token id
    float* mb = g_mid + (size_t)t * HID + role * CC;   // contiguous 8 floats

    if (role == 0) {
        *(float4*)(mb + 0) = make_float4(y[0], y[1], y[2], y[3]);
        *(float4*)(mb + 4) = make_float4(y[4], y[5], y[6], y[7]);
    } else {
        float m = 0.0f;
        #pragma unroll
        for (int c = 0; c < CC; ++c) m += y[c];
        m *= 0.125f;
        float var = 0.0f;
        #pragma unroll
        for (int c = 0; c < CC; ++c) { const float dd = y[c] - m; var = fmaf(dd, dd, var); }
        const float inv = rsqrtf(var * 0.125f + LN_EPS);
        float n[CC];
        #pragma unroll
        for (int c = 0; c < CC; ++c) n[c] = (y[c] - m) * inv * sG[c] + sBt[c];
        *(float4*)(mb + 0) = make_float4(n[0], n[1], n[2], n[3]);
        *(float4*)(mb + 4) = make_float4(n[4], n[5], n[6], n[7]);
    }
}

// ---------------- Kernel 2: dw3x3 + pw1x1 + gate + GEMM 8->48 ----------------
constexpr int TH2 = 8;
constexpr int TW2 = 32;
constexpr int PH2 = TH2 + 2;   // 10
constexpr int PW2 = TW2 + 2;   // 34
constexpr int NT2 = PH2 * PW2; // 340

__global__ __launch_bounds__(THREADS, 4)
void k_back(const float* __restrict__ gdww, const float* __restrict__ gdwb,
            const float* __restrict__ gpww, const float* __restrict__ gpwb,
            const float* __restrict__ gW2, const float* __restrict__ gb2,
            float* __restrict__ out)
{
    __shared__ float sTile[CC][NT2];                 // LN'd x2, halo'd (planar, conflict-free)
    __shared__ __align__(16) float sW2[CC * DIM];
    __shared__ __align__(16) float sb2[DIM];
    __shared__ __align__(16) float sPw[CC * CC];     // rows 32B-aligned -> float4 reads
    __shared__ float sPwb[CC];
    __shared__ __align__(16) float sDw[CC * 12];     // padded stride 12 -> float4 reads
    __shared__ float sDwb[CC];

    const int tid = threadIdx.x;
    for (int i = tid; i < CC * DIM; i += THREADS) sW2[i] = gW2[i];
    if (tid < DIM)     sb2[tid] = gb2[tid];
    if (tid < CC * CC) sPw[tid] = gpww[tid];
    if (tid < CC * 12) {                             // single writer per padded slot
        const int c = tid / 12, tap = tid - c * 12;
        sDw[tid] = (tap < 9) ? gdww[c * 9 + tap] : 0.0f;
    }
    if (tid < CC)      { sPwb[tid] = gpwb[tid]; sDwb[tid] = gdwb[tid]; }

    const int b  = blockIdx.z;
    const int h0 = blockIdx.y * TH2;
    const int w0 = blockIdx.x * TW2;

    // halo'd tile fill: each pixel's 8 LN floats are contiguous (2 LDG.128), planar scatter
    #pragma unroll 1
    for (int p = tid; p < NT2; p += THREADS) {
        const int py = p / PW2;
        const int px = p - py * PW2;
        const int gh = h0 + py - 1;
        const int gw = w0 + px - 1;
        float4 a = make_float4(0.f, 0.f, 0.f, 0.f);
        float4 bq = a;
        if ((unsigned)gh < (unsigned)Hh && (unsigned)gw < (unsigned)Ww) {
            const float* mp = g_mid + (size_t)(b * HW + gh * Ww + gw) * HID + CC;
            a  = *(const float4*)(mp + 0);
            bq = *(const float4*)(mp + 4);
        }
        sTile[0][p] = a.x;  sTile[1][p] = a.y;  sTile[2][p] = a.z;  sTile[3][p] = a.w;
        sTile[4][p] = bq.x; sTile[5][p] = bq.y; sTile[6][p] = bq.z; sTile[7][p] = bq.w;
    }
    __syncthreads();

    const int ty = tid >> 5;
    const int tx = tid & 31;
    const int py = ty + 1;
    const int px = tx + 1;
    const int pix = (h0 + ty) * Ww + (w0 + tx);

    float ncen[CC];
    #pragma unroll
    for (int c = 0; c < CC; ++c) ncen[c] = sTile[c][py * PW2 + px];

    // own token's x1 half: 32 contiguous bytes
    const float4* xq = (const float4*)(g_mid + (size_t)(b * HW + pix) * HID);
    const float4 x1a = __ldg(xq + 0);
    const float4 x1b = __ldg(xq + 1);
    const float x1[CC] = {x1a.x, x1a.y, x1a.z, x1a.w, x1b.x, x1b.y, x1b.z, x1b.w};

    float g[CC];
    #pragma unroll
    for (int c = 0; c < CC; ++c) {
        const float* tp = sTile[c];
        // dw weights: 2 LDS.128 + 1 LDS.32 (padded row, 48B-aligned)
        const float4 ka = *(const float4*)(sDw + c * 12 + 0);   // k0..k3
        const float4 kb = *(const float4*)(sDw + c * 12 + 4);   // k4..k7
        const float  k8 = sDw[c * 12 + 8];
        float acc = sDwb[c];
        {
            const float* r = tp + (py - 1) * PW2 + (px - 1);
            acc = fmaf(r[0], ka.x, acc);
            acc = fmaf(r[1], ka.y, acc);
            acc = fmaf(r[2], ka.z, acc);
        }
        {
            const float* r = tp + py * PW2 + (px - 1);
            acc = fmaf(r[0], ka.w, acc);
            acc = fmaf(r[1], kb.x, acc);
            acc = fmaf(r[2], kb.y, acc);
        }
        {
            const float* r = tp + (py + 1) * PW2 + (px - 1);
            acc = fmaf(r[0], kb.z, acc);
            acc = fmaf(r[1], kb.w, acc);
            acc = fmaf(r[2], k8,   acc);
        }
        // pw weights: 2 LDS.128 per row
        const float4 pa = *(const float4*)(sPw + c * CC + 0);
        const float4 pb = *(const float4*)(sPw + c * CC + 4);
        float chv = sPwb[c];
        chv = fmaf(ncen[0], pa.x, chv);
        chv = fmaf(ncen[1], pa.y, chv);
        chv = fmaf(ncen[2], pa.z, chv);
        chv = fmaf(ncen[3], pa.w, chv);
        chv = fmaf(ncen[4], pb.x, chv);
        chv = fmaf(ncen[5], pb.y, chv);
        chv = fmaf(ncen[6], pb.z, chv);
        chv = fmaf(ncen[7], pb.w, chv);

        g[c] = x1[c] * acc * chv;
    }

    float* op = out + (size_t)b * DIM * HW + pix;
    #pragma unroll
    for (int d4 = 0; d4 < DIM / 4; ++d4) {
        float4 acc = *(const float4*)(sb2 + d4 * 4);
        #pragma unroll
        for (int c = 0; c < CC; ++c) {
            const float4 wv = *(const float4*)(sW2 + c * DIM + d4 * 4);
            const float gc = g[c];
            acc.x = fmaf(gc, wv.x, acc.x);
            acc.y = fmaf(gc, wv.y, acc.y);
            acc.z = fmaf(gc, wv.z, acc.z);
            acc.w = fmaf(gc, wv.w, acc.w);
        }
        op[(size_t)(d4 * 4 + 0) * HW] = acc.x;
        op[(size_t)(d4 * 4 + 1) * HW] = acc.y;
        op[(size_t)(d4 * 4 + 2) * HW] = acc.z;
        op[(size_t)(d4 * 4 + 3) * HW] = acc.w;
    }
}

} // namespace

extern "C" void kernel_launch(void* const* d_in, const int* in_sizes, int n_in,
                              void* d_out, int out_size) {
    const float* x     = (const float*)d_in[0];
    const float* W1    = (const float*)d_in[1];
    const float* b1    = (const float*)d_in[2];
    const float* gamma = (const float*)d_in[3];
    const float* beta  = (const float*)d_in[4];
    const float* dw_w  = (const float*)d_in[5];
    const float* dw_b  = (const float*)d_in[6];
    const float* pw_w  = (const float*)d_in[7];
    const float* pw_b  = (const float*)d_in[8];
    const float* W2    = (const float*)d_in[9];
    const float* b2    = (const float*)d_in[10];
    float* out = (float*)d_out;

    const int dyn1 = TPB1 * XSTRIDE * (int)sizeof(float);   // 26624 B
    cudaFuncSetAttribute(k_front, cudaFuncAttributeMaxDynamicSharedMemorySize, dyn1);

    k_front<<<BATCH * HW / TPB1, THREADS, dyn1>>>(x, W1, b1, gamma, beta);

    dim3 grid2(Ww / TW2, Hh / TH2, BATCH);
    k_back<<<grid2, THREADS>>>(dw_w, dw_b, pw_w, pw_b, W2, b2, out);
}

// round 15
// speedup vs baseline: 1.1521x; 1.0855x over previous
#include <cuda_runtime.h>

namespace {

constexpr int BATCH = 16;
constexpr int DIM   = 48;
constexpr int HID   = 16;
constexpr int CC    = 8;
constexpr int Hh    = 256;
constexpr int Ww    = 256;
constexpr int HW    = Hh * Ww;
constexpr float LN_EPS = 1e-5f;
constexpr int THREADS = 256;
constexpr int TPB1   = 128;   // tokens per block in k_front (2 threads/token)
constexpr int XSTRIDE = 52;   // padded token stride in smem floats

// intermediate, token-interleaved: g_mid[token][16]; ch 0..7 = x1, 8..15 = LN(x2)
__device__ float g_mid[(size_t)BATCH * HW * HID];

__device__ __forceinline__ float tanh_fast(float x) {
    float y;
    asm("tanh.approx.f32 %0, %1;" : "=f"(y) : "f"(x));
    return y;
}

// tanh-form GELU: 0.5*v*(1+tanh(sqrt(2/pi)*(v + 0.044715 v^3)))
__device__ __forceinline__ float gelu_f(float v) {
    const float t = v * v;
    const float inner = fmaf(0.044715f * t, v, v);
    const float h = tanh_fast(0.79788456080286536f * inner);
    const float hv = 0.5f * v;
    return fmaf(hv, h, hv);
}

// ---- packed f32x2 helpers ----
__device__ __forceinline__ unsigned long long pk2(float lo, float hi) {
    unsigned long long r;
    asm("mov.b64 %0, {%1, %2};" : "=l"(r) : "f"(lo), "f"(hi));
    return r;
}
__device__ __forceinline__ void upk2(unsigned long long v, float& lo, float& hi) {
    asm("mov.b64 {%0, %1}, %2;" : "=f"(lo), "=f"(hi) : "l"(v));
}
__device__ __forceinline__ void ffma2(unsigned long long& d,
                                      unsigned long long a, unsigned long long b) {
    asm("fma.rn.f32x2 %0, %1, %2, %3;" : "=l"(d) : "l"(a), "l"(b), "l"(d));
}

// ---------------- Kernel 1: token GEMM 48->16 (2 threads/token), GELUx2, LN ----------------
__global__ __launch_bounds__(THREADS, 4)
void k_front(const float* __restrict__ x,
             const float* __restrict__ gW1, const float* __restrict__ gb1,
             const float* __restrict__ ggamma, const float* __restrict__ gbeta)
{
    __shared__ __align__(16) float sW1[DIM * HID];
    __shared__ float sb1[HID];
    __shared__ float sG[CC], sBt[CC];
    extern __shared__ __align__(16) float sX[];      // 128 tokens * 52 floats

    const int tid = threadIdx.x;
    for (int i = tid; i < DIM * HID; i += THREADS) sW1[i] = gW1[i];
    if (tid < HID) sb1[tid] = gb1[tid];
    if (tid < CC)  { sG[tid] = ggamma[tid]; sBt[tid] = gbeta[tid]; }

    // coalesced stage: this block's 128 tokens (128*12 float4)
    const float4* xg4 = (const float4*)x;
    const size_t base4 = (size_t)blockIdx.x * TPB1 * (DIM / 4);
    #pragma unroll
    for (int i = tid; i < TPB1 * (DIM / 4); i += THREADS) {
        const int tok = i / (DIM / 4);
        const int e4  = i - tok * (DIM / 4);
        *(float4*)(sX + tok * XSTRIDE + e4 * 4) = xg4[base4 + i];
    }
    __syncthreads();

    const int role = tid >> 7;            // 0: x1 half (cols 0-7), 1: x2 half (cols 8-15) + LN
    const int lt   = tid & (TPB1 - 1);
    const int jbase = role * CC;
    const float4* xp = (const float4*)(sX + lt * XSTRIDE);

    unsigned long long yp[4];
    yp[0] = pk2(sb1[jbase + 0], sb1[jbase + 1]);
    yp[1] = pk2(sb1[jbase + 2], sb1[jbase + 3]);
    yp[2] = pk2(sb1[jbase + 4], sb1[jbase + 5]);
    yp[3] = pk2(sb1[jbase + 6], sb1[jbase + 7]);

    #pragma unroll 1
    for (int ch = 0; ch < 3; ++ch) {
        const float4 v0 = xp[ch * 4 + 0], v1 = xp[ch * 4 + 1],
                     v2 = xp[ch * 4 + 2], v3 = xp[ch * 4 + 3];
        const float xs[16] = {v0.x, v0.y, v0.z, v0.w, v1.x, v1.y, v1.z, v1.w,
                              v2.x, v2.y, v2.z, v2.w, v3.x, v3.y, v3.z, v3.w};
        #pragma unroll
        for (int k = 0; k < 16; ++k) {
            const int d = ch * 16 + k;
            const ulonglong2* wp = (const ulonglong2*)(sW1 + d * HID + jbase);
            const ulonglong2 wA = wp[0], wB = wp[1];
            const unsigned long long xv2 = pk2(xs[k], xs[k]);
            ffma2(yp[0], xv2, wA.x);
            ffma2(yp[1], xv2, wA.y);
            ffma2(yp[2], xv2, wB.x);
            ffma2(yp[3], xv2, wB.y);
        }
    }

    float y[CC];
    upk2(yp[0], y[0], y[1]);
    upk2(yp[1], y[2], y[3]);
    upk2(yp[2], y[4], y[5]);
    upk2(yp[3], y[6], y[7]);

    #pragma unroll
    for (int j = 0; j < CC; ++j) y[j] = gelu_f(gelu_f(y[j]));

    const int t = blockIdx.x * TPB1 + lt;              // token id
    float* mb = g_mid + (size_t)t * HID + role * CC;   // contiguous 8 floats

    if (role == 0) {
        *(float4*)(mb + 0) = make_float4(y[0], y[1], y[2], y[3]);
        *(float4*)(mb + 4) = make_float4(y[4], y[5], y[6], y[7]);
    } else {
        float m = 0.0f;
        #pragma unroll
        for (int c = 0; c < CC; ++c) m += y[c];
        m *= 0.125f;
        float var = 0.0f;
        #pragma unroll
        for (int c = 0; c < CC; ++c) { const float dd = y[c] - m; var = fmaf(dd, dd, var); }
        const float inv = rsqrtf(var * 0.125f + LN_EPS);
        float n[CC];
        #pragma unroll
        for (int c = 0; c < CC; ++c) n[c] = (y[c] - m) * inv * sG[c] + sBt[c];
        *(float4*)(mb + 0) = make_float4(n[0], n[1], n[2], n[3]);
        *(float4*)(mb + 4) = make_float4(n[4], n[5], n[6], n[7]);
    }
}

// ---------------- Kernel 2: dw3x3 + pw1x1 + gate + GEMM 8->48 ----------------
constexpr int TH2 = 8;
constexpr int TW2 = 32;
constexpr int PH2 = TH2 + 2;   // 10
constexpr int PW2 = TW2 + 2;   // 34
constexpr int NT2 = PH2 * PW2; // 340

__global__ __launch_bounds__(THREADS, 4)
void k_back(const float* __restrict__ gdww, const float* __restrict__ gdwb,
            const float* __restrict__ gpww, const float* __restrict__ gpwb,
            const float* __restrict__ gW2, const float* __restrict__ gb2,
            float* __restrict__ out)
{
    __shared__ float sTile[CC][NT2];                 // LN'd x2, halo'd (planar, conflict-free)
    __shared__ __align__(16) float sW2[CC * DIM];
    __shared__ __align__(16) float sb2[DIM];
    __shared__ __align__(16) float sPw[CC * CC];     // rows 32B-aligned -> float4 reads
    __shared__ float sPwb[CC];
    __shared__ __align__(16) float sDw[CC * 12];     // padded stride 12 -> float4 reads
    __shared__ float sDwb[CC];

    const int tid = threadIdx.x;
    for (int i = tid; i < CC * DIM; i += THREADS) sW2[i] = gW2[i];
    if (tid < DIM)     sb2[tid] = gb2[tid];
    if (tid < CC * CC) sPw[tid] = gpww[tid];
    if (tid < CC * 12) {                             // single writer per padded slot
        const int c = tid / 12, tap = tid - c * 12;
        sDw[tid] = (tap < 9) ? gdww[c * 9 + tap] : 0.0f;
    }
    if (tid < CC)      { sPwb[tid] = gpwb[tid]; sDwb[tid] = gdwb[tid]; }

    const int b  = blockIdx.z;
    const int h0 = blockIdx.y * TH2;
    const int w0 = blockIdx.x * TW2;

    // halo'd tile fill: each pixel's 8 LN floats are contiguous (2 LDG.128), planar scatter
    #pragma unroll 1
    for (int p = tid; p < NT2; p += THREADS) {
        const int py = p / PW2;
        const int px = p - py * PW2;
        const int gh = h0 + py - 1;
        const int gw = w0 + px - 1;
        float4 a = make_float4(0.f, 0.f, 0.f, 0.f);
        float4 bq = a;
        if ((unsigned)gh < (unsigned)Hh && (unsigned)gw < (unsigned)Ww) {
            const float* mp = g_mid + (size_t)(b * HW + gh * Ww + gw) * HID + CC;
            a  = *(const float4*)(mp + 0);
            bq = *(const float4*)(mp + 4);
        }
        sTile[0][p] = a.x;  sTile[1][p] = a.y;  sTile[2][p] = a.z;  sTile[3][p] = a.w;
        sTile[4][p] = bq.x; sTile[5][p] = bq.y; sTile[6][p] = bq.z; sTile[7][p] = bq.w;
    }
    __syncthreads();

    const int ty = tid >> 5;
    const int tx = tid & 31;
    const int py = ty + 1;
    const int px = tx + 1;
    const int pix = (h0 + ty) * Ww + (w0 + tx);

    float ncen[CC];
    #pragma unroll
    for (int c = 0; c < CC; ++c) ncen[c] = sTile[c][py * PW2 + px];

    // own token's x1 half: 32 contiguous bytes
    const float4* xq = (const float4*)(g_mid + (size_t)(b * HW + pix) * HID);
    const float4 x1a = __ldg(xq + 0);
    const float4 x1b = __ldg(xq + 1);
    const float x1[CC] = {x1a.x, x1a.y, x1a.z, x1a.w, x1b.x, x1b.y, x1b.z, x1b.w};

    float g[CC];
    #pragma unroll
    for (int c = 0; c < CC; ++c) {
        const float* tp = sTile[c];
        // dw weights: 2 LDS.128 + 1 LDS.32 (padded row, 48B-aligned)
        const float4 ka = *(const float4*)(sDw + c * 12 + 0);   // k0..k3
        const float4 kb = *(const float4*)(sDw + c * 12 + 4);   // k4..k7
        const float  k8 = sDw[c * 12 + 8];
        float acc = sDwb[c];
        {
            const float* r = tp + (py - 1) * PW2 + (px - 1);
            acc = fmaf(r[0], ka.x, acc);
            acc = fmaf(r[1], ka.y, acc);
            acc = fmaf(r[2], ka.z, acc);
        }
        {
            const float* r = tp + py * PW2 + (px - 1);
            acc = fmaf(r[0], ka.w, acc);
            acc = fmaf(r[1], kb.x, acc);
            acc = fmaf(r[2], kb.y, acc);
        }
        {
            const float* r = tp + (py + 1) * PW2 + (px - 1);
            acc = fmaf(r[0], kb.z, acc);
            acc = fmaf(r[1], kb.w, acc);
            acc = fmaf(r[2], k8,   acc);
        }
        // pw weights: 2 LDS.128 per row
        const float4 pa = *(const float4*)(sPw + c * CC + 0);
        const float4 pb = *(const float4*)(sPw + c * CC + 4);
        float chv = sPwb[c];
        chv = fmaf(ncen[0], pa.x, chv);
        chv = fmaf(ncen[1], pa.y, chv);
        chv = fmaf(ncen[2], pa.z, chv);
        chv = fmaf(ncen[3], pa.w, chv);
        chv = fmaf(ncen[4], pb.x, chv);
        chv = fmaf(ncen[5], pb.y, chv);
        chv = fmaf(ncen[6], pb.z, chv);
        chv = fmaf(ncen[7], pb.w, chv);

        g[c] = x1[c] * acc * chv;
    }

    float* op = out + (size_t)b * DIM * HW + pix;
    #pragma unroll
    for (int d4 = 0; d4 < DIM / 4; ++d4) {
        float4 acc = *(const float4*)(sb2 + d4 * 4);
        #pragma unroll
        for (int c = 0; c < CC; ++c) {
            const float4 wv = *(const float4*)(sW2 + c * DIM + d4 * 4);
            const float gc = g[c];
            acc.x = fmaf(gc, wv.x, acc.x);
            acc.y = fmaf(gc, wv.y, acc.y);
            acc.z = fmaf(gc, wv.z, acc.z);
            acc.w = fmaf(gc, wv.w, acc.w);
        }
        op[(size_t)(d4 * 4 + 0) * HW] = acc.x;
        op[(size_t)(d4 * 4 + 1) * HW] = acc.y;
        op[(size_t)(d4 * 4 + 2) * HW] = acc.z;
        op[(size_t)(d4 * 4 + 3) * HW] = acc.w;
    }
}

} // namespace

extern "C" void kernel_launch(void* const* d_in, const int* in_sizes, int n_in,
                              void* d_out, int out_size) {
    const float* x     = (const float*)d_in[0];
    const float* W1    = (const float*)d_in[1];
    const float* b1    = (const float*)d_in[2];
    const float* gamma = (const float*)d_in[3];
    const float* beta  = (const float*)d_in[4];
    const float* dw_w  = (const float*)d_in[5];
    const float* dw_b  = (const float*)d_in[6];
    const float* pw_w  = (const float*)d_in[7];
    const float* pw_b  = (const float*)d_in[8];
    const float* W2    = (const float*)d_in[9];
    const float* b2    = (const float*)d_in[10];
    float* out = (float*)d_out;

    const int dyn1 = TPB1 * XSTRIDE * (int)sizeof(float);   // 26624 B
    cudaFuncSetAttribute(k_front, cudaFuncAttributeMaxDynamicSharedMemorySize, dyn1);

    k_front<<<BATCH * HW / TPB1, THREADS, dyn1>>>(x, W1, b1, gamma, beta);

    dim3 grid2(Ww / TW2, Hh / TH2, BATCH);
    k_back<<<grid2, THREADS>>>(dw_w, dw_b, pw_w, pw_b, W2, b2, out);
}

// round 16
// speedup vs baseline: 1.2531x; 1.0876x over previous
#include <cuda_runtime.h>

namespace {

constexpr int BATCH = 16;
constexpr int DIM   = 48;
constexpr int HID   = 16;
constexpr int CC    = 8;
constexpr int Hh    = 256;
constexpr int Ww    = 256;
constexpr int HW    = Hh * Ww;
constexpr float LN_EPS = 1e-5f;
constexpr int THREADS = 256;
constexpr int TPB1   = 256;   // tokens per block in k_front (2 tokens per thread, 2 thr-roles)
constexpr int XSTRIDE = 52;   // padded token stride in smem floats (conflict-free float4)

// intermediate, token-interleaved: g_mid[token][16]; ch 0..7 = x1, 8..15 = LN(x2)
__device__ float g_mid[(size_t)BATCH * HW * HID];

__device__ __forceinline__ float tanh_fast(float x) {
    float y;
    asm("tanh.approx.f32 %0, %1;" : "=f"(y) : "f"(x));
    return y;
}

// tanh-form GELU: 0.5*v*(1+tanh(sqrt(2/pi)*(v + 0.044715 v^3)))
__device__ __forceinline__ float gelu_f(float v) {
    const float t = v * v;
    const float inner = fmaf(0.044715f * t, v, v);
    const float h = tanh_fast(0.79788456080286536f * inner);
    const float hv = 0.5f * v;
    return fmaf(hv, h, hv);
}

// ---- packed f32x2 helpers ----
__device__ __forceinline__ unsigned long long pk2(float lo, float hi) {
    unsigned long long r;
    asm("mov.b64 %0, {%1, %2};" : "=l"(r) : "f"(lo), "f"(hi));
    return r;
}
__device__ __forceinline__ void upk2(unsigned long long v, float& lo, float& hi) {
    asm("mov.b64 {%0, %1}, %2;" : "=f"(lo), "=f"(hi) : "l"(v));
}
__device__ __forceinline__ void ffma2(unsigned long long& d,
                                      unsigned long long a, unsigned long long b) {
    asm("fma.rn.f32x2 %0, %1, %2, %3;" : "=l"(d) : "l"(a), "l"(b), "l"(d));
}

// ---------------- Kernel 1: token GEMM 48->16, 2 tokens/thread, shared weight loads ----------------
__global__ __launch_bounds__(THREADS, 3)
void k_front(const float* __restrict__ x,
             const float* __restrict__ gW1, const float* __restrict__ gb1,
             const float* __restrict__ ggamma, const float* __restrict__ gbeta)
{
    __shared__ __align__(16) float sW1[DIM * HID];
    __shared__ float sb1[HID];
    __shared__ float sG[CC], sBt[CC];
    extern __shared__ __align__(16) float sX[];      // 256 tokens * 52 floats

    const int tid = threadIdx.x;
    for (int i = tid; i < DIM * HID; i += THREADS) sW1[i] = gW1[i];
    if (tid < HID) sb1[tid] = gb1[tid];
    if (tid < CC)  { sG[tid] = ggamma[tid]; sBt[tid] = gbeta[tid]; }

    // coalesced stage: this block's 256 tokens (256*12 float4)
    const float4* xg4 = (const float4*)x;
    const size_t base4 = (size_t)blockIdx.x * TPB1 * (DIM / 4);
    #pragma unroll
    for (int i = tid; i < TPB1 * (DIM / 4); i += THREADS) {
        const int tok = i / (DIM / 4);
        const int e4  = i - tok * (DIM / 4);
        *(float4*)(sX + tok * XSTRIDE + e4 * 4) = xg4[base4 + i];
    }
    __syncthreads();

    const int role = tid >> 7;            // 0: x1 half (cols 0-7), 1: x2 half (cols 8-15) + LN
    const int lt   = tid & 127;           // first token; second is lt+128
    const int jbase = role * CC;
    const float4* xpA = (const float4*)(sX + lt * XSTRIDE);
    const float4* xpB = (const float4*)(sX + (lt + 128) * XSTRIDE);

    unsigned long long ypA[4], ypB[4];
    ypA[0] = pk2(sb1[jbase + 0], sb1[jbase + 1]);
    ypA[1] = pk2(sb1[jbase + 2], sb1[jbase + 3]);
    ypA[2] = pk2(sb1[jbase + 4], sb1[jbase + 5]);
    ypA[3] = pk2(sb1[jbase + 6], sb1[jbase + 7]);
    ypB[0] = ypA[0]; ypB[1] = ypA[1]; ypB[2] = ypA[2]; ypB[3] = ypA[3];

    #pragma unroll 1
    for (int ch = 0; ch < 6; ++ch) {                 // 8 input dims per chunk
        const float4 a0 = xpA[ch * 2 + 0], a1 = xpA[ch * 2 + 1];
        const float4 b0 = xpB[ch * 2 + 0], b1 = xpB[ch * 2 + 1];
        const float xsA[8] = {a0.x, a0.y, a0.z, a0.w, a1.x, a1.y, a1.z, a1.w};
        const float xsB[8] = {b0.x, b0.y, b0.z, b0.w, b1.x, b1.y, b1.z, b1.w};
        #pragma unroll
        for (int k = 0; k < 8; ++k) {
            const int d = ch * 8 + k;
            const ulonglong2* wp = (const ulonglong2*)(sW1 + d * HID + jbase);
            const ulonglong2 wA = wp[0], wB = wp[1];   // shared by both tokens
            const unsigned long long xa = pk2(xsA[k], xsA[k]);
            const unsigned long long xb = pk2(xsB[k], xsB[k]);
            ffma2(ypA[0], xa, wA.x);
            ffma2(ypB[0], xb, wA.x);
            ffma2(ypA[1], xa, wA.y);
            ffma2(ypB[1], xb, wA.y);
            ffma2(ypA[2], xa, wB.x);
            ffma2(ypB[2], xb, wB.x);
            ffma2(ypA[3], xa, wB.y);
            ffma2(ypB[3], xb, wB.y);
        }
    }

    const int t0 = blockIdx.x * TPB1 + lt;             // first token id

    #pragma unroll
    for (int half = 0; half < 2; ++half) {
        float y[CC];
        unsigned long long* yp = half ? ypB : ypA;
        upk2(yp[0], y[0], y[1]);
        upk2(yp[1], y[2], y[3]);
        upk2(yp[2], y[4], y[5]);
        upk2(yp[3], y[6], y[7]);

        #pragma unroll
        for (int j = 0; j < CC; ++j) y[j] = gelu_f(gelu_f(y[j]));

        const int t = t0 + half * 128;
        float* mb = g_mid + (size_t)t * HID + role * CC;

        if (role == 0) {
            *(float4*)(mb + 0) = make_float4(y[0], y[1], y[2], y[3]);
            *(float4*)(mb + 4) = make_float4(y[4], y[5], y[6], y[7]);
        } else {
            float m = 0.0f;
            #pragma unroll
            for (int c = 0; c < CC; ++c) m += y[c];
            m *= 0.125f;
            float var = 0.0f;
            #pragma unroll
            for (int c = 0; c < CC; ++c) { const float dd = y[c] - m; var = fmaf(dd, dd, var); }
            const float inv = rsqrtf(var * 0.125f + LN_EPS);
            float n[CC];
            #pragma unroll
            for (int c = 0; c < CC; ++c) n[c] = (y[c] - m) * inv * sG[c] + sBt[c];
            *(float4*)(mb + 0) = make_float4(n[0], n[1], n[2], n[3]);
            *(float4*)(mb + 4) = make_float4(n[4], n[5], n[6], n[7]);
        }
    }
}

// ---------------- Kernel 2: dw3x3 + pw1x1 + gate + GEMM 8->48 (R13 proven) ----------------
constexpr int TH2 = 8;
constexpr int TW2 = 32;
constexpr int PH2 = TH2 + 2;   // 10
constexpr int PW2 = TW2 + 2;   // 34
constexpr int NT2 = PH2 * PW2; // 340

__global__ __launch_bounds__(THREADS, 4)
void k_back(const float* __restrict__ gdww, const float* __restrict__ gdwb,
            const float* __restrict__ gpww, const float* __restrict__ gpwb,
            const float* __restrict__ gW2, const float* __restrict__ gb2,
            float* __restrict__ out)
{
    __shared__ float sTile[CC][NT2];                 // LN'd x2, halo'd (planar, conflict-free)
    __shared__ __align__(16) float sW2[CC * DIM];
    __shared__ __align__(16) float sb2[DIM];
    __shared__ __align__(16) float sPw[CC * CC];     // rows 32B-aligned -> float4 reads
    __shared__ float sPwb[CC];
    __shared__ __align__(16) float sDw[CC * 12];     // padded stride 12 -> float4 reads
    __shared__ float sDwb[CC];

    const int tid = threadIdx.x;
    for (int i = tid; i < CC * DIM; i += THREADS) sW2[i] = gW2[i];
    if (tid < DIM)     sb2[tid] = gb2[tid];
    if (tid < CC * CC) sPw[tid] = gpww[tid];
    if (tid < CC * 12) {                             // single writer per padded slot
        const int c = tid / 12, tap = tid - c * 12;
        sDw[tid] = (tap < 9) ? gdww[c * 9 + tap] : 0.0f;
    }
    if (tid < CC)      { sPwb[tid] = gpwb[tid]; sDwb[tid] = gdwb[tid]; }

    const int b  = blockIdx.z;
    const int h0 = blockIdx.y * TH2;
    const int w0 = blockIdx.x * TW2;

    // halo'd tile fill: each pixel's 8 LN floats are contiguous (2 LDG.128), planar scatter
    #pragma unroll 1
    for (int p = tid; p < NT2; p += THREADS) {
        const int py = p / PW2;
        const int px = p - py * PW2;
        const int gh = h0 + py - 1;
        const int gw = w0 + px - 1;
        float4 a = make_float4(0.f, 0.f, 0.f, 0.f);
        float4 bq = a;
        if ((unsigned)gh < (unsigned)Hh && (unsigned)gw < (unsigned)Ww) {
            const float* mp = g_mid + (size_t)(b * HW + gh * Ww + gw) * HID + CC;
            a  = *(const float4*)(mp + 0);
            bq = *(const float4*)(mp + 4);
        }
        sTile[0][p] = a.x;  sTile[1][p] = a.y;  sTile[2][p] = a.z;  sTile[3][p] = a.w;
        sTile[4][p] = bq.x; sTile[5][p] = bq.y; sTile[6][p] = bq.z; sTile[7][p] = bq.w;
    }
    __syncthreads();

    const int ty = tid >> 5;
    const int tx = tid & 31;
    const int py = ty + 1;
    const int px = tx + 1;
    const int pix = (h0 + ty) * Ww + (w0 + tx);

    float ncen[CC];
    #pragma unroll
    for (int c = 0; c < CC; ++c) ncen[c] = sTile[c][py * PW2 + px];

    // own token's x1 half: 32 contiguous bytes
    const float4* xq = (const float4*)(g_mid + (size_t)(b * HW + pix) * HID);
    const float4 x1a = __ldg(xq + 0);
    const float4 x1b = __ldg(xq + 1);
    const float x1[CC] = {x1a.x, x1a.y, x1a.z, x1a.w, x1b.x, x1b.y, x1b.z, x1b.w};

    float g[CC];
    #pragma unroll
    for (int c = 0; c < CC; ++c) {
        const float* tp = sTile[c];
        const float4 ka = *(const float4*)(sDw + c * 12 + 0);   // k0..k3
        const float4 kb = *(const float4*)(sDw + c * 12 + 4);   // k4..k7
        const float  k8 = sDw[c * 12 + 8];
        float acc = sDwb[c];
        {
            const float* r = tp + (py - 1) * PW2 + (px - 1);
            acc = fmaf(r[0], ka.x, acc);
            acc = fmaf(r[1], ka.y, acc);
            acc = fmaf(r[2], ka.z, acc);
        }
        {
            const float* r = tp + py * PW2 + (px - 1);
            acc = fmaf(r[0], ka.w, acc);
            acc = fmaf(r[1], kb.x, acc);
            acc = fmaf(r[2], kb.y, acc);
        }
        {
            const float* r = tp + (py + 1) * PW2 + (px - 1);
            acc = fmaf(r[0], kb.z, acc);
            acc = fmaf(r[1], kb.w, acc);
            acc = fmaf(r[2], k8,   acc);
        }
        const float4 pa = *(const float4*)(sPw + c * CC + 0);
        const float4 pb = *(const float4*)(sPw + c * CC + 4);
        float chv = sPwb[c];
        chv = fmaf(ncen[0], pa.x, chv);
        chv = fmaf(ncen[1], pa.y, chv);
        chv = fmaf(ncen[2], pa.z, chv);
        chv = fmaf(ncen[3], pa.w, chv);
        chv = fmaf(ncen[4], pb.x, chv);
        chv = fmaf(ncen[5], pb.y, chv);
        chv = fmaf(ncen[6], pb.z, chv);
        chv = fmaf(ncen[7], pb.w, chv);

        g[c] = x1[c] * acc * chv;
    }

    float* op = out + (size_t)b * DIM * HW + pix;
    #pragma unroll
    for (int d4 = 0; d4 < DIM / 4; ++d4) {
        float4 acc = *(const float4*)(sb2 + d4 * 4);
        #pragma unroll
        for (int c = 0; c < CC; ++c) {
            const float4 wv = *(const float4*)(sW2 + c * DIM + d4 * 4);
            const float gc = g[c];
            acc.x = fmaf(gc, wv.x, acc.x);
            acc.y = fmaf(gc, wv.y, acc.y);
            acc.z = fmaf(gc, wv.z, acc.z);
            acc.w = fmaf(gc, wv.w, acc.w);
        }
        op[(size_t)(d4 * 4 + 0) * HW] = acc.x;
        op[(size_t)(d4 * 4 + 1) * HW] = acc.y;
        op[(size_t)(d4 * 4 + 2) * HW] = acc.z;
        op[(size_t)(d4 * 4 + 3) * HW] = acc.w;
    }
}

} // namespace

extern "C" void kernel_launch(void* const* d_in, const int* in_sizes, int n_in,
                              void* d_out, int out_size) {
    const float* x     = (const float*)d_in[0];
    const float* W1    = (const float*)d_in[1];
    const float* b1    = (const float*)d_in[2];
    const float* gamma = (const float*)d_in[3];
    const float* beta  = (const float*)d_in[4];
    const float* dw_w  = (const float*)d_in[5];
    const float* dw_b  = (const float*)d_in[6];
    const float* pw_w  = (const float*)d_in[7];
    const float* pw_b  = (const float*)d_in[8];
    const float* W2    = (const float*)d_in[9];
    const float* b2    = (const float*)d_in[10];
    float* out = (float*)d_out;

    const int dyn1 = TPB1 * XSTRIDE * (int)sizeof(float);   // 53248 B
    cudaFuncSetAttribute(k_front, cudaFuncAttributeMaxDynamicSharedMemorySize, dyn1);

    k_front<<<BATCH * HW / TPB1, THREADS, dyn1>>>(x, W1, b1, gamma, beta);

    dim3 grid2(Ww / TW2, Hh / TH2, BATCH);
    k_back<<<grid2, THREADS>>>(dw_w, dw_b, pw_w, pw_b, W2, b2, out);
}